// round 2
// baseline (speedup 1.0000x reference)
#include <cuda_runtime.h>

// Problem constants (fixed by the dataset)
#define NATOMS 6144
#define FDIM   128
#define HDIM   64      // F/2
#define NMOL   48
#define NBLK   148     // one block per SM -> all co-resident, grid barrier safe
#define NTHR   256
#define NWTOT  (NBLK * (NTHR / 32))   // 1184 warps
#define ACAP   64      // smem atom-row capacity (actual per-block count is 41..42)

// Scratch (device globals — no allocations allowed). All writes are
// deterministic overwrites; nothing needs zero-init between graph replays.
__device__ float  g_q[NATOMS];        // raw charge (pre-neutralization)
__device__ float  g_sc6[NATOMS];      // sqrt(softplus(c6))
__device__ float  g_mu3[NATOMS * 3];  // dipole vectors
__device__ int    g_segs[NMOL];       // molecule start (batch is sorted)
__device__ int    g_sege[NMOL];       // molecule end (exclusive)
__device__ double g_partial[NBLK];    // per-block energy partials
__device__ volatile int g_sense;      // barrier sense (flips each use)
__device__ int    g_count;            // barrier arrival counter (self-resetting)

__device__ __forceinline__ void grid_barrier() {
    __syncthreads();
    if (threadIdx.x == 0) {
        int s = g_sense;              // read sense BEFORE arriving
        __threadfence();              // publish this block's global writes
        if (atomicAdd(&g_count, 1) == NBLK - 1) {
            g_count = 0;              // reset for next barrier / next replay
            __threadfence();
            g_sense = s ^ 1;          // release
        } else {
            while (g_sense == s) { }  // volatile spin (1 thread per block)
        }
    }
    __syncthreads();
    __threadfence();
}

extern "C" __global__ void __launch_bounds__(NTHR, 1) fused_kernel(
    const float* __restrict__ h0, const float* __restrict__ h1,
    const float* __restrict__ pos, const int* __restrict__ batch,
    const float* __restrict__ qW1, const float* __restrict__ qb1,
    const float* __restrict__ qW2, const float* __restrict__ qb2,
    const float* __restrict__ cW1, const float* __restrict__ cb1,
    const float* __restrict__ cW2, const float* __restrict__ cb2,
    const float* __restrict__ muW, float* __restrict__ out)
{
    extern __shared__ float smem[];
    float (*sH0)[FDIM] = (float(*)[FDIM])smem;     // ACAP x 128 floats (32 KB)
    float* sW = smem + ACAP * FDIM;                // 128 x 64 floats   (32 KB)
    __shared__ float  sPart[8][8];
    __shared__ double sD[8];

    const int tid  = threadIdx.x;
    const int bid  = blockIdx.x;
    const int w    = tid >> 5;
    const int lane = tid & 31;

    // ---- Phase 1: per-atom MLPs on this block's atom range -----------------
    const int astart = (bid * NATOMS) / NBLK;
    const int aend   = ((bid + 1) * NATOMS) / NBLK;
    const int acnt   = aend - astart;              // 41 or 42 (always > 32)

    // stage h0 rows (coalesced), zero-pad to ACAP
    for (int idx = tid; idx < ACAP * FDIM; idx += NTHR) {
        int a = idx >> 7, f = idx & 127;
        sH0[a][f] = (a < acnt) ? h0[(size_t)(astart + a) * FDIM + f] : 0.0f;
    }

    const int t   = tid & 63;   // hidden unit owned by this thread
    const int grp = tid >> 6;   // 4 groups of 8 atoms per 32-atom pass

    for (int phase = 0; phase < 2; phase++) {
        const float* W1 = phase ? cW1 : qW1;
        const float* B1 = phase ? cb1 : qb1;
        const float* W2 = phase ? cW2 : qW2;
        const float* B2 = phase ? cb2 : qb2;

        __syncthreads();
        for (int idx = tid; idx < FDIM * HDIM; idx += NTHR) sW[idx] = W1[idx];
        __syncthreads();

        const float bias1 = B1[t];
        const float w2c   = W2[t];

        for (int p = 0; p < 2; p++) {              // 2 passes x 32 atoms
            float hid[8];
            #pragma unroll
            for (int a = 0; a < 8; a++) hid[a] = 0.0f;

            #pragma unroll 8
            for (int f4 = 0; f4 < FDIM / 4; f4++) {
                const float w0 = sW[(4 * f4 + 0) * HDIM + t];
                const float w1 = sW[(4 * f4 + 1) * HDIM + t];
                const float w2 = sW[(4 * f4 + 2) * HDIM + t];
                const float w3 = sW[(4 * f4 + 3) * HDIM + t];
                #pragma unroll
                for (int a = 0; a < 8; a++) {
                    const float4 h = *reinterpret_cast<const float4*>(
                        &sH0[p * 32 + grp * 8 + a][4 * f4]);
                    hid[a] = fmaf(h.x, w0, hid[a]);
                    hid[a] = fmaf(h.y, w1, hid[a]);
                    hid[a] = fmaf(h.z, w2, hid[a]);
                    hid[a] = fmaf(h.w, w3, hid[a]);
                }
            }

            float v[8];
            #pragma unroll
            for (int a = 0; a < 8; a++) {
                float x = hid[a] + bias1;
                float s = 1.0f / (1.0f + expf(-x));  // sigmoid
                v[a] = x * s * w2c;                   // silu * W2 column
            }
            #pragma unroll
            for (int a = 0; a < 8; a++) {
                #pragma unroll
                for (int o = 16; o > 0; o >>= 1)
                    v[a] += __shfl_down_sync(0xffffffffu, v[a], o);
            }
            if (lane == 0) {
                #pragma unroll
                for (int a = 0; a < 8; a++) sPart[w][a] = v[a];
            }
            __syncthreads();
            if (tid < 32) {                           // local atoms p*32 + tid
                const int g2 = tid >> 3, a = tid & 7;
                const float val = sPart[2 * g2][a] + sPart[2 * g2 + 1][a] + B2[0];
                const int loc = p * 32 + tid;
                if (loc < acnt) {
                    const int i = astart + loc;
                    if (phase == 0) {
                        g_q[i] = val;
                    } else {
                        const float sp = fmaxf(val, 0.0f) + log1pf(expf(-fabsf(val)));
                        g_sc6[i] = sqrtf(sp);
                    }
                }
            }
            __syncthreads();                          // sPart reuse
        }
    }

    // mu = h1 @ muW : reuse sW[0..127]
    __syncthreads();
    if (tid < FDIM) sW[tid] = muW[tid];
    __syncthreads();
    for (int loc = w; loc < acnt; loc += 8) {
        const int i = astart + loc;
        const float* hrow = h1 + (size_t)i * 3 * FDIM;
        #pragma unroll
        for (int d = 0; d < 3; d++) {
            float pacc = 0.0f;
            #pragma unroll
            for (int f = lane; f < FDIM; f += 32)
                pacc = fmaf(hrow[d * FDIM + f], sW[f], pacc);
            #pragma unroll
            for (int o = 16; o > 0; o >>= 1)
                pacc += __shfl_down_sync(0xffffffffu, pacc, o);
            if (lane == 0) g_mu3[3 * i + d] = pacc;
        }
    }

    // segment boundaries via boundary detection (deterministic overwrite)
    if (tid < acnt) {
        const int i = astart + tid;
        const int b = batch[i];
        if (i == 0 || batch[i - 1] != b) g_segs[b] = i;
        if (i == NATOMS - 1 || batch[i + 1] != b) g_sege[b] = i + 1;
    }

    grid_barrier();

    // ---- Phase 2: pairwise energy, warps strided over atoms i --------------
    // i<j only (all three terms are symmetric -> drop the reference's 0.5).
    const int gw = bid * 8 + w;
    double acc = 0.0;

    for (int i = gw; i < NATOMS; i += NWTOT) {
        const int b  = batch[i];
        const int s0 = g_segs[b];
        const int e0 = g_sege[b];

        // per-molecule mean charge (warp-cooperative, butterfly broadcast)
        float qs = 0.0f;
        for (int k = s0 + lane; k < e0; k += 32) qs += g_q[k];
        #pragma unroll
        for (int o = 16; o > 0; o >>= 1)
            qs += __shfl_xor_sync(0xffffffffu, qs, o);
        const float qm = qs / (float)(e0 - s0);

        const float qi  = g_q[i] - qm;
        const float pix = pos[3 * i], piy = pos[3 * i + 1], piz = pos[3 * i + 2];
        const float si  = g_sc6[i];
        const float mix = g_mu3[3 * i], miy = g_mu3[3 * i + 1], miz = g_mu3[3 * i + 2];

        float facc = 0.0f;   // short fp32 run (<= ~5 iters), promoted once below
        for (int j = i + 1 + lane; j < e0; j += 32) {
            const float dx = pix - pos[3 * j];
            const float dy = piy - pos[3 * j + 1];
            const float dz = piz - pos[3 * j + 2];
            const float d2r  = dx * dx + dy * dy + dz * dz;   // raw dist_sq
            const float d2   = d2r + 1e-8f;
            const float invd = rsqrtf(d2);                    // MUFU 1
            const float dist = d2 * invd;

            // Coulomb
            const float qj    = g_q[j] - qm;
            const float taper = 1.0f - __expf(-0.5f * dist);  // MUFU 2
            const float ec    = qi * qj * invd * taper * 14.399f;

            // shared reciprocal for vdW + dipole denominators   (MUFU 3)
            const float r6    = d2r * d2r * d2r;
            const float aden  = r6 + 20.0f;
            const float bden  = d2r * dist + 10.0f;
            const float invab = __fdividef(1.0f, aden * bden);

            const float ev = -si * g_sc6[j] * (invab * bden);

            const float mjx = g_mu3[3 * j], mjy = g_mu3[3 * j + 1], mjz = g_mu3[3 * j + 2];
            const float mumu = mix * mjx + miy * mjy + miz * mjz;
            const float di   = (mix * dx + miy * dy + miz * dz) * invd;
            const float dj   = (mjx * dx + mjy * dy + mjz * dz) * invd;
            const float ed   = (mumu - 3.0f * di * dj) * (invab * aden);

            facc += ec + ev + ed;
        }
        acc += (double)facc;
    }

    // warp reduce (double), block partial (deterministic overwrite)
    #pragma unroll
    for (int o = 16; o > 0; o >>= 1)
        acc += __shfl_down_sync(0xffffffffu, acc, o);
    if (lane == 0) sD[w] = acc;
    __syncthreads();
    if (tid == 0) {
        double ts = 0.0;
        #pragma unroll
        for (int k = 0; k < 8; k++) ts += sD[k];
        g_partial[bid] = ts;
    }

    grid_barrier();

    // ---- Phase 3: block 0 reduces the 148 partials and writes the scalar ---
    if (bid == 0) {
        double v = (tid < NBLK) ? g_partial[tid] : 0.0;
        #pragma unroll
        for (int o = 16; o > 0; o >>= 1)
            v += __shfl_down_sync(0xffffffffu, v, o);
        if (lane == 0) sD[w] = v;
        __syncthreads();
        if (tid == 0) {
            double tot = 0.0;
            #pragma unroll
            for (int k = 0; k < 8; k++) tot += sD[k];
            out[0] = (float)tot;    // LONG_RANGE_SCALE = 1.0
        }
    }
}

// ---------------------------------------------------------------------------
extern "C" void kernel_launch(void* const* d_in, const int* in_sizes, int n_in,
                              void* d_out, int out_size) {
    const float* h0    = (const float*)d_in[0];
    const float* h1    = (const float*)d_in[1];
    const float* pos   = (const float*)d_in[2];
    const int*   batch = (const int*)  d_in[3];
    const float* qW1   = (const float*)d_in[4];
    const float* qb1   = (const float*)d_in[5];
    const float* qW2   = (const float*)d_in[6];
    const float* qb2   = (const float*)d_in[7];
    const float* cW1   = (const float*)d_in[8];
    const float* cb1   = (const float*)d_in[9];
    const float* cW2   = (const float*)d_in[10];
    const float* cb2   = (const float*)d_in[11];
    const float* muW   = (const float*)d_in[12];

    const int smem_bytes = (ACAP * FDIM + FDIM * HDIM) * sizeof(float); // 64 KB
    cudaFuncSetAttribute(fused_kernel,
                         cudaFuncAttributeMaxDynamicSharedMemorySize, smem_bytes);
    fused_kernel<<<NBLK, NTHR, smem_bytes>>>(
        h0, h1, pos, batch,
        qW1, qb1, qW2, qb2,
        cW1, cb1, cW2, cb2,
        muW, (float*)d_out);
}

// round 3
// speedup vs baseline: 1.9656x; 1.9656x over previous
#include <cuda_runtime.h>
#include <cstdint>

// Problem constants (fixed by the dataset)
#define NATOMS 6144
#define FDIM   128
#define HDIM   64      // F/2
#define NMOL   48
#define NBLK   148     // <= SM count on both B300(148) and GB300(152); all co-resident
#define NTHR   768
#define NWARP  (NTHR / 32)            // 24
#define NWTOT  (NBLK * NWARP)         // 3552 warps
#define ASLOT  48                     // atom slots per block (acnt is 41..42)

// Scratch (device globals). All writes are deterministic overwrites; nothing
// needs zero-init between graph replays.
__device__ float4 g_A[NATOMS];        // pos.x, pos.y, pos.z, q_raw
__device__ float4 g_B[NATOMS];        // mu.x, mu.y, mu.z, sqrt(softplus(c6))
__device__ int    g_segs[NMOL];       // molecule start (batch sorted)
__device__ int    g_sege[NMOL];       // molecule end (exclusive)
__device__ double g_partial[NBLK];    // per-block energy partials
__device__ volatile int g_sense;      // barrier sense
__device__ int    g_count;            // barrier counter (self-resetting)

__device__ __forceinline__ void grid_barrier() {
    __syncthreads();
    if (threadIdx.x == 0) {
        int s = g_sense;
        __threadfence();
        if (atomicAdd(&g_count, 1) == NBLK - 1) {
            g_count = 0;
            __threadfence();
            g_sense = s ^ 1;
        } else {
            while (g_sense == s) { }
        }
    }
    __syncthreads();
    __threadfence();
}

__device__ __forceinline__ void cpa16(uint32_t s, const float* g) {
    asm volatile("cp.async.cg.shared.global [%0], [%1], 16;" :: "r"(s), "l"(g));
}
#define CPA_COMMIT() asm volatile("cp.async.commit_group;")
#define CPA_WAIT(n)  asm volatile("cp.async.wait_group %0;" :: "n"(n))

extern "C" __global__ void __launch_bounds__(NTHR, 1) fused_kernel(
    const float* __restrict__ h0, const float* __restrict__ h1,
    const float* __restrict__ pos, const int* __restrict__ batch,
    const float* __restrict__ qW1, const float* __restrict__ qb1,
    const float* __restrict__ qW2, const float* __restrict__ qb2,
    const float* __restrict__ cW1, const float* __restrict__ cb1,
    const float* __restrict__ cW2, const float* __restrict__ cb2,
    const float* __restrict__ muW, float* __restrict__ out)
{
    extern __shared__ float smem[];
    float* sH0 = smem;                         // 48*128 = 6144 floats (24 KB)
    float* sWq = smem + ASLOT * FDIM;          // 128*64  = 8192 floats (32 KB)
    float* sWc = sWq + FDIM * HDIM;            // 8192 floats (32 KB)
    float* sH1 = sWc + FDIM * HDIM;            // 48*384 = 18432 floats (72 KB)

    __shared__ float  sPart[NWARP][4];
    __shared__ float  s_q[ASLOT];
    __shared__ float  s_sc6[ASLOT];
    __shared__ float  s_mu[ASLOT][3];
    __shared__ float  s_muW[FDIM];
    __shared__ float  s_qmean[NMOL];
    __shared__ double sDD[NWARP];

    const int tid  = threadIdx.x;
    const int bid  = blockIdx.x;
    const int w    = tid >> 5;
    const int lane = tid & 31;

    const int astart = (bid * NATOMS) / NBLK;
    const int aend   = ((bid + 1) * NATOMS) / NBLK;
    const int acnt   = aend - astart;          // 41 or 42

    // ---- Prologue: async staging --------------------------------------------
    const uint32_t sH0u = (uint32_t)__cvta_generic_to_shared(sH0);
    const uint32_t sWqu = (uint32_t)__cvta_generic_to_shared(sWq);
    const uint32_t sWcu = (uint32_t)__cvta_generic_to_shared(sWc);
    const uint32_t sH1u = (uint32_t)__cvta_generic_to_shared(sH1);

    // G0: qW1 + h0 rows
    for (int idx = tid; idx < FDIM * HDIM / 4; idx += NTHR)
        cpa16(sWqu + idx * 16, qW1 + idx * 4);
    for (int idx = tid; idx < acnt * FDIM / 4; idx += NTHR)
        cpa16(sH0u + idx * 16, h0 + (size_t)astart * FDIM + idx * 4);
    CPA_COMMIT();
    // G1: cW1
    for (int idx = tid; idx < FDIM * HDIM / 4; idx += NTHR)
        cpa16(sWcu + idx * 16, cW1 + idx * 4);
    CPA_COMMIT();
    // G2: h1 rows (the big 63 KB DRAM stream, overlapped with the MLP below)
    for (int idx = tid; idx < acnt * 3 * FDIM / 4; idx += NTHR)
        cpa16(sH1u + idx * 16, h1 + (size_t)astart * 3 * FDIM + idx * 4);
    CPA_COMMIT();

    // zero-pad sH0 rows acnt..47 (plain stores, disjoint from cp.async targets)
    for (int idx = tid; idx < (ASLOT - acnt) * FDIM; idx += NTHR)
        sH0[acnt * FDIM + idx] = 0.0f;

    // ---- Phase 1: q / c6 MLPs ----------------------------------------------
    // t = hidden unit (0..63), grp owns 4 atom slots. 12 groups x 4 = 48 slots.
    const int t   = tid & 63;
    const int grp = tid >> 6;

    CPA_WAIT(2);              // qW1 + h0 ready
    __syncthreads();

    #pragma unroll
    for (int phase = 0; phase < 2; phase++) {
        const float* sW = phase ? sWc : sWq;
        const float* B1 = phase ? cb1 : qb1;
        const float* W2 = phase ? cW2 : qW2;
        const float* B2 = phase ? cb2 : qb2;

        if (phase == 1) { CPA_WAIT(1); __syncthreads(); }

        if (grp * 4 < acnt) {            // skip all-pad groups
            float hid[4] = {0.f, 0.f, 0.f, 0.f};
            #pragma unroll 8
            for (int f4 = 0; f4 < FDIM / 4; f4++) {
                const float w0 = sW[(4 * f4 + 0) * HDIM + t];
                const float w1 = sW[(4 * f4 + 1) * HDIM + t];
                const float w2 = sW[(4 * f4 + 2) * HDIM + t];
                const float w3 = sW[(4 * f4 + 3) * HDIM + t];
                #pragma unroll
                for (int a = 0; a < 4; a++) {
                    const float4 h = *reinterpret_cast<const float4*>(
                        &sH0[(grp * 4 + a) * FDIM + 4 * f4]);
                    hid[a] = fmaf(h.x, w0, hid[a]);
                    hid[a] = fmaf(h.y, w1, hid[a]);
                    hid[a] = fmaf(h.z, w2, hid[a]);
                    hid[a] = fmaf(h.w, w3, hid[a]);
                }
            }
            const float bias1 = B1[t];
            const float w2c   = W2[t];
            float v[4];
            #pragma unroll
            for (int a = 0; a < 4; a++) {
                const float x = hid[a] + bias1;
                const float s = __fdividef(1.0f, 1.0f + __expf(-x));  // sigmoid
                v[a] = x * s * w2c;                                    // silu * W2
            }
            #pragma unroll
            for (int a = 0; a < 4; a++) {
                #pragma unroll
                for (int o = 16; o > 0; o >>= 1)
                    v[a] += __shfl_down_sync(0xffffffffu, v[a], o);
            }
            if (lane == 0) {
                #pragma unroll
                for (int a = 0; a < 4; a++) sPart[w][a] = v[a];
            }
        }
        __syncthreads();
        if (tid < acnt) {
            const int g2 = tid >> 2, k = tid & 3;
            const float val = sPart[2 * g2][k] + sPart[2 * g2 + 1][k] + B2[0];
            if (phase == 0) {
                s_q[tid] = val;
            } else {
                const float sp = fmaxf(val, 0.0f) + log1pf(__expf(-fabsf(val)));
                s_sc6[tid] = sqrtf(sp);
            }
        }
        __syncthreads();
    }

    // ---- mu = h1 @ muW (from smem) -----------------------------------------
    CPA_WAIT(0);
    if (tid < FDIM) s_muW[tid] = muW[tid];
    __syncthreads();
    for (int loc = w; loc < acnt; loc += NWARP) {
        const float* hr = &sH1[loc * 3 * FDIM];
        float m0 = 0.f, m1 = 0.f, m2 = 0.f;
        #pragma unroll
        for (int f = lane; f < FDIM; f += 32) {
            const float wv = s_muW[f];
            m0 = fmaf(hr[f], wv, m0);
            m1 = fmaf(hr[FDIM + f], wv, m1);
            m2 = fmaf(hr[2 * FDIM + f], wv, m2);
        }
        #pragma unroll
        for (int o = 16; o > 0; o >>= 1) {
            m0 += __shfl_down_sync(0xffffffffu, m0, o);
            m1 += __shfl_down_sync(0xffffffffu, m1, o);
            m2 += __shfl_down_sync(0xffffffffu, m2, o);
        }
        if (lane == 0) { s_mu[loc][0] = m0; s_mu[loc][1] = m1; s_mu[loc][2] = m2; }
    }
    __syncthreads();

    // ---- pack per-atom data + segment boundaries ---------------------------
    if (tid < acnt) {
        const int i = astart + tid;
        g_A[i] = make_float4(pos[3 * i], pos[3 * i + 1], pos[3 * i + 2], s_q[tid]);
        g_B[i] = make_float4(s_mu[tid][0], s_mu[tid][1], s_mu[tid][2], s_sc6[tid]);
        const int b = batch[i];
        if (i == 0 || batch[i - 1] != b) g_segs[b] = i;
        if (i == NATOMS - 1 || batch[i + 1] != b) g_sege[b] = i + 1;
    }

    grid_barrier();

    // ---- per-molecule mean charge (each block computes all 48 into smem) ---
    for (int m = w; m < NMOL; m += NWARP) {
        const int s0 = g_segs[m], e0 = g_sege[m];
        float qs = 0.0f;
        for (int k = s0 + lane; k < e0; k += 32) qs += g_A[k].w;
        #pragma unroll
        for (int o = 16; o > 0; o >>= 1)
            qs += __shfl_xor_sync(0xffffffffu, qs, o);
        if (lane == 0) s_qmean[m] = (e0 > s0) ? qs / (float)(e0 - s0) : 0.0f;
    }
    __syncthreads();

    // ---- Phase 2: pairwise energy (i<j only; all terms symmetric) ----------
    double acc = 0.0;
    for (int i = bid * NWARP + w; i < NATOMS; i += NWTOT) {
        const int b  = batch[i];
        const int e0 = g_sege[b];
        const float qm = s_qmean[b];

        const float4 Ai = g_A[i];
        const float4 Bi = g_B[i];
        const float qi = Ai.w - qm;

        float facc = 0.0f;
        for (int j = i + 1 + lane; j < e0; j += 32) {
            const float4 Aj = g_A[j];
            const float4 Bj = g_B[j];
            const float dx = Ai.x - Aj.x;
            const float dy = Ai.y - Aj.y;
            const float dz = Ai.z - Aj.z;
            const float d2r  = dx * dx + dy * dy + dz * dz;
            const float d2   = d2r + 1e-8f;
            const float invd = rsqrtf(d2);                    // MUFU 1
            const float dist = d2 * invd;

            // Coulomb
            const float qj    = Aj.w - qm;
            const float taper = 1.0f - __expf(-0.5f * dist);  // MUFU 2
            const float ec    = qi * qj * invd * taper * 14.399f;

            // shared reciprocal for vdW + dipole denominators (MUFU 3)
            const float r6    = d2r * d2r * d2r;
            const float aden  = r6 + 20.0f;
            const float bden  = d2r * dist + 10.0f;
            const float invab = __fdividef(1.0f, aden * bden);

            const float ev = -Bi.w * Bj.w * (invab * bden);

            const float mumu = Bi.x * Bj.x + Bi.y * Bj.y + Bi.z * Bj.z;
            const float di   = (Bi.x * dx + Bi.y * dy + Bi.z * dz) * invd;
            const float dj   = (Bj.x * dx + Bj.y * dy + Bj.z * dz) * invd;
            const float ed   = (mumu - 3.0f * di * dj) * (invab * aden);

            facc += ec + ev + ed;
        }
        acc += (double)facc;
    }

    #pragma unroll
    for (int o = 16; o > 0; o >>= 1)
        acc += __shfl_down_sync(0xffffffffu, acc, o);
    if (lane == 0) sDD[w] = acc;
    __syncthreads();
    if (tid == 0) {
        double ts = 0.0;
        #pragma unroll
        for (int k = 0; k < NWARP; k++) ts += sDD[k];
        g_partial[bid] = ts;
    }

    grid_barrier();

    // ---- Phase 3: block 0 reduces the 148 partials -------------------------
    if (bid == 0) {
        double v = (tid < NBLK) ? g_partial[tid] : 0.0;
        #pragma unroll
        for (int o = 16; o > 0; o >>= 1)
            v += __shfl_down_sync(0xffffffffu, v, o);
        if (lane == 0 && w < 5) sDD[w] = v;
        __syncthreads();
        if (tid == 0) {
            double tot = 0.0;
            #pragma unroll
            for (int k = 0; k < 5; k++) tot += sDD[k];
            out[0] = (float)tot;    // LONG_RANGE_SCALE = 1.0
        }
    }
}

// ---------------------------------------------------------------------------
extern "C" void kernel_launch(void* const* d_in, const int* in_sizes, int n_in,
                              void* d_out, int out_size) {
    const float* h0    = (const float*)d_in[0];
    const float* h1    = (const float*)d_in[1];
    const float* pos   = (const float*)d_in[2];
    const int*   batch = (const int*)  d_in[3];
    const float* qW1   = (const float*)d_in[4];
    const float* qb1   = (const float*)d_in[5];
    const float* qW2   = (const float*)d_in[6];
    const float* qb2   = (const float*)d_in[7];
    const float* cW1   = (const float*)d_in[8];
    const float* cb1   = (const float*)d_in[9];
    const float* cW2   = (const float*)d_in[10];
    const float* cb2   = (const float*)d_in[11];
    const float* muW   = (const float*)d_in[12];

    const int smem_bytes = (ASLOT * FDIM + 2 * FDIM * HDIM + ASLOT * 3 * FDIM)
                           * (int)sizeof(float);   // 160 KB
    cudaFuncSetAttribute(fused_kernel,
                         cudaFuncAttributeMaxDynamicSharedMemorySize, smem_bytes);
    fused_kernel<<<NBLK, NTHR, smem_bytes>>>(
        h0, h1, pos, batch,
        qW1, qb1, qW2, qb2,
        cW1, cb1, cW2, cb2,
        muW, (float*)d_out);
}

// round 4
// speedup vs baseline: 2.1919x; 1.1151x over previous
#include <cuda_runtime.h>
#include <cstdint>

// Problem constants (fixed by the dataset)
#define NATOMS 6144
#define FDIM   128
#define HDIM   64      // F/2
#define NMOL   48
#define NBLK   148     // co-resident on B300(148)/GB300(152)
#define NTHR   768
#define NWARP  24
#define NWTOT  (NBLK * NWARP)
#define ASLOT  48      // padded atom slots per block (acnt is 41..42)
#define NPAIR  24      // ASLOT/2

// Device-global scratch. All writes are deterministic overwrites (graph-replay safe).
__device__ float4 g_A[NATOMS];        // pos.xyz, q_raw
__device__ float4 g_B[NATOMS];        // mu.xyz, sqrt(softplus(c6))
__device__ int    g_segs[NMOL];
__device__ int    g_sege[NMOL];
__device__ double g_partial[NBLK];
__device__ volatile int g_sense;
__device__ int    g_count;

__device__ __forceinline__ void grid_barrier() {
    __syncthreads();
    if (threadIdx.x == 0) {
        int s = g_sense;
        __threadfence();
        if (atomicAdd(&g_count, 1) == NBLK - 1) {
            g_count = 0;
            __threadfence();
            g_sense = s ^ 1;
        } else {
            while (g_sense == s) { }
        }
    }
    __syncthreads();
    __threadfence();
}

// ---- f32x2 packed-FMA helpers (sm_100+; FFMA2 in SASS) ---------------------
__device__ __forceinline__ long long dupf(float w) {
    long long d; unsigned r = __float_as_uint(w);
    asm("mov.b64 %0, {%1, %1};" : "=l"(d) : "r"(r));
    return d;
}
__device__ __forceinline__ void ffma2(long long& a, long long h, long long w) {
    asm("fma.rn.f32x2 %0, %1, %2, %0;" : "+l"(a) : "l"(h), "l"(w));
}
__device__ __forceinline__ void unpack2(long long a, float& lo, float& hi) {
    unsigned l, h;
    asm("mov.b64 {%0, %1}, %2;" : "=r"(l), "=r"(h) : "l"(a));
    lo = __uint_as_float(l); hi = __uint_as_float(h);
}

// ---- TMA 1-D bulk copy + mbarrier ------------------------------------------
__device__ __forceinline__ void tma_bulk_1d(uint32_t dst, const void* src,
                                            uint32_t bytes, uint32_t mbar) {
    asm volatile(
        "cp.async.bulk.shared::cta.global.mbarrier::complete_tx::bytes [%0], [%1], %2, [%3];"
        :: "r"(dst), "l"(src), "r"(bytes), "r"(mbar) : "memory");
}

extern "C" __global__ void __launch_bounds__(NTHR, 1) fused_kernel(
    const float* __restrict__ h0, const float* __restrict__ h1,
    const float* __restrict__ pos, const int* __restrict__ batch,
    const float* __restrict__ qW1, const float* __restrict__ qb1,
    const float* __restrict__ qW2, const float* __restrict__ qb2,
    const float* __restrict__ cW1, const float* __restrict__ cb1,
    const float* __restrict__ cW2, const float* __restrict__ cb2,
    const float* __restrict__ muW, float* __restrict__ out)
{
    extern __shared__ float smem[];
    float* sH0  = smem;                        // 48*128 floats (24 KB, TMA dst)
    float* sWq  = smem + ASLOT * FDIM;         // 128*64 (32 KB, TMA dst)
    float* sWc  = sWq + FDIM * HDIM;           // 128*64 (32 KB, TMA dst)
    float* sH0P = sWc + FDIM * HDIM;           // pair-major: 24 pairs x 128 float2 (24 KB)

    __shared__ float  sPQ[4][2][12];           // q-MLP partials
    __shared__ float  sPC[4][2][12];           // c6-MLP partials
    __shared__ float  s_mu[ASLOT][3];
    __shared__ float  s_qmean[NMOL];
    __shared__ double sDD[NWARP];
    __shared__ __align__(8) unsigned long long mbar[1];

    const int tid  = threadIdx.x;
    const int bid  = blockIdx.x;
    const int w    = tid >> 5;
    const int lane = tid & 31;

    const int astart = (bid * NATOMS) / NBLK;
    const int aend   = ((bid + 1) * NATOMS) / NBLK;
    const int acnt   = aend - astart;          // 41 or 42

    const uint32_t mb   = (uint32_t)__cvta_generic_to_shared(mbar);
    const uint32_t sH0u = (uint32_t)__cvta_generic_to_shared(sH0);
    const uint32_t sWqu = (uint32_t)__cvta_generic_to_shared(sWq);
    const uint32_t sWcu = (uint32_t)__cvta_generic_to_shared(sWc);

    // ---- Prologue: 3 bulk TMA copies on one mbarrier -----------------------
    const uint32_t h0_bytes = (uint32_t)acnt * FDIM * 4u;
    if (tid == 0) {
        asm volatile("mbarrier.init.shared.b64 [%0], 1;" :: "r"(mb) : "memory");
    }
    __syncthreads();
    if (tid == 0) {
        const uint32_t total = 2u * FDIM * HDIM * 4u + h0_bytes;
        asm volatile("mbarrier.arrive.expect_tx.shared.b64 _, [%0], %1;"
                     :: "r"(mb), "r"(total) : "memory");
        tma_bulk_1d(sWqu, qW1, FDIM * HDIM * 4u, mb);
        tma_bulk_1d(sWcu, cW1, FDIM * HDIM * 4u, mb);
        tma_bulk_1d(sH0u, h0 + (size_t)astart * FDIM, h0_bytes, mb);
    }
    // all threads wait (acquire orders TMA smem writes before our reads)
    {
        asm volatile(
            "{\n\t.reg .pred P;\n"
            "WAIT_%=:\n\t"
            "mbarrier.try_wait.parity.acquire.cta.shared::cta.b64 P, [%0], 0, 0x989680;\n\t"
            "@!P bra WAIT_%=;\n\t}"
            :: "r"(mb) : "memory");
    }

    // ---- Transform h0 to pair-major f32x2 layout ---------------------------
    // sH0P word index for (atom a, feature f): (a>>1)*256 + f*2 + (a&1)
    for (int idx = tid; idx < ASLOT * FDIM; idx += NTHR) {
        const int a = idx >> 7, f = idx & 127;
        const float v = (a < acnt) ? sH0[a * FDIM + f] : 0.0f;
        sH0P[(a >> 1) * 256 + f * 2 + (a & 1)] = v;
    }
    __syncthreads();

    // ---- Warp-specialized compute: q-MLP | c6-MLP | mu-GEMV ----------------
    if (w < 16) {
        // warps 0-7: q-MLP, warps 8-15: c6-MLP. Local layout: 256 threads,
        // t = hidden unit (0..63), grp = atom group (4 groups x 12 atoms).
        const int sec = (w >> 3);              // 0 = q, 1 = c6
        const int ql  = tid - (sec << 8);      // 0..255
        const int t   = ql & 63;
        const int grp = ql >> 6;               // 0..3
        const int hw  = (ql >> 5) & 1;         // half of the 64-unit span
        const float* sW = sec ? sWc : sWq;
        const float* B1 = sec ? cb1 : qb1;
        const float* W2 = sec ? cW2 : qW2;

        long long acc[6] = {0, 0, 0, 0, 0, 0}; // 6 atom-pairs (12 atoms)
        const int pb = grp * 6;                // first pair of this group

        #pragma unroll 2
        for (int f4 = 0; f4 < FDIM / 4; f4++) {
            const float w0 = sW[(4 * f4 + 0) * HDIM + t];
            const float w1 = sW[(4 * f4 + 1) * HDIM + t];
            const float w2 = sW[(4 * f4 + 2) * HDIM + t];
            const float w3 = sW[(4 * f4 + 3) * HDIM + t];
            const long long d0 = dupf(w0), d1 = dupf(w1);
            const long long d2 = dupf(w2), d3 = dupf(w3);
            #pragma unroll
            for (int p = 0; p < 6; p++) {
                const double2* hp = reinterpret_cast<const double2*>(
                    &sH0P[(pb + p) * 256 + f4 * 8]);
                const double2 hA = hp[0];      // packed {f, f+1}
                const double2 hB = hp[1];      // packed {f+2, f+3}
                ffma2(acc[p], __double_as_longlong(hA.x), d0);
                ffma2(acc[p], __double_as_longlong(hA.y), d1);
                ffma2(acc[p], __double_as_longlong(hB.x), d2);
                ffma2(acc[p], __double_as_longlong(hB.y), d3);
            }
        }

        const float bias1 = B1[t];
        const float w2c   = W2[t];
        float v[12];
        #pragma unroll
        for (int p = 0; p < 6; p++) {
            float a0, a1; unpack2(acc[p], a0, a1);
            const float x0 = a0 + bias1, x1 = a1 + bias1;
            v[2 * p]     = x0 * __fdividef(1.0f, 1.0f + __expf(-x0)) * w2c;
            v[2 * p + 1] = x1 * __fdividef(1.0f, 1.0f + __expf(-x1)) * w2c;
        }
        #pragma unroll
        for (int k = 0; k < 12; k++) {
            #pragma unroll
            for (int o = 16; o > 0; o >>= 1)
                v[k] += __shfl_down_sync(0xffffffffu, v[k], o);
        }
        if (lane == 0) {
            float (*dst)[2][12] = sec ? sPC : sPQ;
            #pragma unroll
            for (int k = 0; k < 12; k++) dst[grp][hw][k] = v[k];
        }
    } else {
        // warps 16-23: mu = h1 @ muW, directly from global (coalesced LDG.128)
        const int mw = w - 16;
        const float4 mw4 = *reinterpret_cast<const float4*>(muW + lane * 4);
        for (int loc = mw; loc < acnt; loc += 8) {
            const float* hr = h1 + (size_t)(astart + loc) * 3 * FDIM;
            float m[3];
            #pragma unroll
            for (int d = 0; d < 3; d++) {
                const float4 hv = *reinterpret_cast<const float4*>(
                    hr + d * FDIM + lane * 4);
                m[d] = hv.x * mw4.x + hv.y * mw4.y + hv.z * mw4.z + hv.w * mw4.w;
            }
            #pragma unroll
            for (int o = 16; o > 0; o >>= 1) {
                m[0] += __shfl_down_sync(0xffffffffu, m[0], o);
                m[1] += __shfl_down_sync(0xffffffffu, m[1], o);
                m[2] += __shfl_down_sync(0xffffffffu, m[2], o);
            }
            if (lane == 0) { s_mu[loc][0] = m[0]; s_mu[loc][1] = m[1]; s_mu[loc][2] = m[2]; }
        }
    }
    __syncthreads();

    // ---- Pack per-atom pair data + segment boundaries ----------------------
    if (tid < acnt) {
        const int grp = tid / 12, idx = tid % 12;
        const float qv  = sPQ[grp][0][idx] + sPQ[grp][1][idx] + qb2[0];
        const float cv  = sPC[grp][0][idx] + sPC[grp][1][idx] + cb2[0];
        const float sp  = fmaxf(cv, 0.0f) + log1pf(__expf(-fabsf(cv)));
        const int i = astart + tid;
        g_A[i] = make_float4(pos[3 * i], pos[3 * i + 1], pos[3 * i + 2], qv);
        g_B[i] = make_float4(s_mu[tid][0], s_mu[tid][1], s_mu[tid][2], sqrtf(sp));
        const int b = batch[i];
        if (i == 0 || batch[i - 1] != b) g_segs[b] = i;
        if (i == NATOMS - 1 || batch[i + 1] != b) g_sege[b] = i + 1;
    }

    grid_barrier();

    // ---- Per-molecule mean charge ------------------------------------------
    for (int m = w; m < NMOL; m += NWARP) {
        const int s0 = g_segs[m], e0 = g_sege[m];
        float qs = 0.0f;
        for (int k = s0 + lane; k < e0; k += 32) qs += g_A[k].w;
        #pragma unroll
        for (int o = 16; o > 0; o >>= 1)
            qs += __shfl_xor_sync(0xffffffffu, qs, o);
        if (lane == 0) s_qmean[m] = (e0 > s0) ? qs / (float)(e0 - s0) : 0.0f;
    }
    __syncthreads();

    // ---- Pairwise energy (i<j only; all three terms symmetric) -------------
    double acc = 0.0;
    for (int i = bid * NWARP + w; i < NATOMS; i += NWTOT) {
        const int b  = batch[i];
        const int e0 = g_sege[b];
        const float qm = s_qmean[b];

        const float4 Ai = g_A[i];
        const float4 Bi = g_B[i];
        const float qi = Ai.w - qm;

        float facc = 0.0f;
        for (int j = i + 1 + lane; j < e0; j += 32) {
            const float4 Aj = g_A[j];
            const float4 Bj = g_B[j];
            const float dx = Ai.x - Aj.x;
            const float dy = Ai.y - Aj.y;
            const float dz = Ai.z - Aj.z;
            const float d2r  = dx * dx + dy * dy + dz * dz;
            const float d2   = d2r + 1e-8f;
            const float invd = rsqrtf(d2);                    // MUFU 1
            const float dist = d2 * invd;

            const float qj    = Aj.w - qm;
            const float taper = 1.0f - __expf(-0.5f * dist);  // MUFU 2
            const float ec    = qi * qj * invd * taper * 14.399f;

            const float r6    = d2r * d2r * d2r;
            const float aden  = r6 + 20.0f;
            const float bden  = d2r * dist + 10.0f;
            const float invab = __fdividef(1.0f, aden * bden); // MUFU 3

            const float ev = -Bi.w * Bj.w * (invab * bden);

            const float mumu = Bi.x * Bj.x + Bi.y * Bj.y + Bi.z * Bj.z;
            const float di   = (Bi.x * dx + Bi.y * dy + Bi.z * dz) * invd;
            const float dj   = (Bj.x * dx + Bj.y * dy + Bj.z * dz) * invd;
            const float ed   = (mumu - 3.0f * di * dj) * (invab * aden);

            facc += ec + ev + ed;
        }
        acc += (double)facc;
    }

    #pragma unroll
    for (int o = 16; o > 0; o >>= 1)
        acc += __shfl_down_sync(0xffffffffu, acc, o);
    if (lane == 0) sDD[w] = acc;
    __syncthreads();
    if (tid == 0) {
        double ts = 0.0;
        #pragma unroll
        for (int k = 0; k < NWARP; k++) ts += sDD[k];
        g_partial[bid] = ts;
    }

    grid_barrier();

    // ---- Block 0 reduces the 148 partials ----------------------------------
    if (bid == 0) {
        double v = (tid < NBLK) ? g_partial[tid] : 0.0;
        #pragma unroll
        for (int o = 16; o > 0; o >>= 1)
            v += __shfl_down_sync(0xffffffffu, v, o);
        if (lane == 0 && w < 5) sDD[w] = v;
        __syncthreads();
        if (tid == 0) {
            double tot = 0.0;
            #pragma unroll
            for (int k = 0; k < 5; k++) tot += sDD[k];
            out[0] = (float)tot;    // LONG_RANGE_SCALE = 1.0
        }
    }
}

// ---------------------------------------------------------------------------
extern "C" void kernel_launch(void* const* d_in, const int* in_sizes, int n_in,
                              void* d_out, int out_size) {
    const float* h0    = (const float*)d_in[0];
    const float* h1    = (const float*)d_in[1];
    const float* pos   = (const float*)d_in[2];
    const int*   batch = (const int*)  d_in[3];
    const float* qW1   = (const float*)d_in[4];
    const float* qb1   = (const float*)d_in[5];
    const float* qW2   = (const float*)d_in[6];
    const float* qb2   = (const float*)d_in[7];
    const float* cW1   = (const float*)d_in[8];
    const float* cb1   = (const float*)d_in[9];
    const float* cW2   = (const float*)d_in[10];
    const float* cb2   = (const float*)d_in[11];
    const float* muW   = (const float*)d_in[12];

    const int smem_bytes = (ASLOT * FDIM       // sH0
                            + 2 * FDIM * HDIM  // sWq + sWc
                            + ASLOT * FDIM)    // sH0P
                           * (int)sizeof(float);   // 112 KB
    cudaFuncSetAttribute(fused_kernel,
                         cudaFuncAttributeMaxDynamicSharedMemorySize, smem_bytes);
    fused_kernel<<<NBLK, NTHR, smem_bytes>>>(
        h0, h1, pos, batch,
        qW1, qb1, qW2, qb2,
        cW1, cb1, cW2, cb2,
        muW, (float*)d_out);
}